// round 1
// baseline (speedup 1.0000x reference)
#include <cuda_runtime.h>
#include <stdint.h>

#define N_ATOM   6144
#define NTOT     (3 * N_ATOM)          /* 18432 floats */
#define TPB      512
#define TILE     512
#define TSTRIPS  (N_ATOM / TILE)       /* 12 */
#define NTILES   (TSTRIPS * (TSTRIPS + 1) / 2)   /* 78 */
#define NQBLK    4
#define GRID     (NQBLK + 1 + NTILES)  /* 83 */
#define SMEM_BYTES (NTOT * 4)          /* 73728: quantile keys; pairwise uses a prefix */

static const double NPAIRS_D   = 18871296.0;   /* 6144*6143/2 */
static const double THRESH_MIN = 0.8;
static const double RAND_STD   = 1.75;
static const double IQR_RAND   = 2.45;

__device__ double g_pair_partial[NTILES];
__device__ double g_sum_d, g_sumsq_d;
__device__ float  g_qv[4];

__device__ __forceinline__ float sqrt_approx(float x) {
    float r;
    asm("sqrt.approx.f32 %0, %1;" : "=f"(r) : "f"(x));
    return r;
}

// monotone float -> uint key (order preserving)
__device__ __forceinline__ unsigned fkey(float f) {
    unsigned u = __float_as_uint(f);
    return (u & 0x80000000u) ? ~u : (u | 0x80000000u);
}
__device__ __forceinline__ float funkey(unsigned u) {
    unsigned bits = (u & 0x80000000u) ? (u & 0x7fffffffu) : ~u;
    return __uint_as_float(bits);
}

__global__ void __launch_bounds__(TPB)
dp_main_kernel(const float* __restrict__ g) {
    extern __shared__ unsigned char smem_raw[];
    const int bid = blockIdx.x;
    const int t   = threadIdx.x;

    if (bid < NQBLK) {
        // ---- exact k-th order statistic via 32-bit radix bisection ----
        unsigned* keys = (unsigned*)smem_raw;       // 18432 u32 = 72KB
        __shared__ unsigned s_cnt[TPB / 32];
        __shared__ unsigned s_r;
        const int ks[4] = {4607, 4608, 13823, 13824};
        const unsigned k = (unsigned)ks[bid];

        #pragma unroll
        for (int e = t; e < NTOT; e += TPB)
            keys[e] = fkey(g[e]);
        if (t == 0) s_r = 0u;
        __syncthreads();

        for (int b = 31; b >= 0; --b) {
            const unsigned cand = s_r + (1u << b);
            unsigned c = 0;
            #pragma unroll
            for (int e = t; e < NTOT; e += TPB)
                c += (keys[e] < cand) ? 1u : 0u;
            #pragma unroll
            for (int o = 16; o; o >>= 1)
                c += __shfl_down_sync(0xffffffffu, c, o);
            if ((t & 31) == 0) s_cnt[t >> 5] = c;
            __syncthreads();
            if (t == 0) {
                unsigned tot = 0;
                #pragma unroll
                for (int w = 0; w < TPB / 32; ++w) tot += s_cnt[w];
                if (tot <= k) s_r = cand;   // largest r with count(<r) <= k  ==  v[k]
            }
            __syncthreads();
        }
        if (t == 0) g_qv[bid] = funkey(s_r);

    } else if (bid == NQBLK) {
        // ---- std sums (fp64, deterministic) ----
        __shared__ double sds[TPB / 32], sdq[TPB / 32];
        double s = 0.0, s2 = 0.0;
        #pragma unroll
        for (int e = t; e < NTOT; e += TPB) {
            double v = (double)g[e];
            s += v; s2 += v * v;
        }
        #pragma unroll
        for (int o = 16; o; o >>= 1) {
            s  += __shfl_down_sync(0xffffffffu, s,  o);
            s2 += __shfl_down_sync(0xffffffffu, s2, o);
        }
        if ((t & 31) == 0) { sds[t >> 5] = s; sdq[t >> 5] = s2; }
        __syncthreads();
        if (t == 0) {
            double a = 0.0, b2 = 0.0;
            #pragma unroll
            for (int w = 0; w < TPB / 32; ++w) { a += sds[w]; b2 += sdq[w]; }
            g_sum_d = a; g_sumsq_d = b2;
        }

    } else {
        // ---- pairwise penalty, triangular tile (a, b), a <= b ----
        const int idx = bid - (NQBLK + 1);
        int a = 0, rem = idx;
        while (rem >= TSTRIPS - a) { rem -= TSTRIPS - a; ++a; }
        const int b = a + rem;

        float* sx  = (float*)smem_raw;
        float* sy  = sx + TILE;
        float* sz  = sy + TILE;
        float* red = sz + TILE;

        const int j = b * TILE + t;
        sx[t] = g[3 * j + 0];
        sy[t] = g[3 * j + 1];
        sz[t] = g[3 * j + 2];
        __syncthreads();

        const int i = a * TILE + t;
        const float xi = g[3 * i + 0];
        const float yi = g[3 * i + 1];
        const float zi = g[3 * i + 2];

        float acc0 = 0.f, acc1 = 0.f, acc2 = 0.f, acc3 = 0.f;

        if (a == b) {
            // diagonal tile: only jj > t
            for (int jj = t + 1; jj < TILE; ++jj) {
                float dx = xi - sx[jj], dy = yi - sy[jj], dz = zi - sz[jj];
                float sq = fmaf(dz, dz, fmaf(dy, dy, dx * dx));
                acc0 += fmaxf(0.8f - sqrt_approx(sq), 0.0f);
            }
        } else {
            #pragma unroll 1
            for (int jj = 0; jj < TILE; jj += 4) {
                {
                    float dx = xi - sx[jj+0], dy = yi - sy[jj+0], dz = zi - sz[jj+0];
                    float sq = fmaf(dz, dz, fmaf(dy, dy, dx * dx));
                    acc0 += fmaxf(0.8f - sqrt_approx(sq), 0.0f);
                }
                {
                    float dx = xi - sx[jj+1], dy = yi - sy[jj+1], dz = zi - sz[jj+1];
                    float sq = fmaf(dz, dz, fmaf(dy, dy, dx * dx));
                    acc1 += fmaxf(0.8f - sqrt_approx(sq), 0.0f);
                }
                {
                    float dx = xi - sx[jj+2], dy = yi - sy[jj+2], dz = zi - sz[jj+2];
                    float sq = fmaf(dz, dz, fmaf(dy, dy, dx * dx));
                    acc2 += fmaxf(0.8f - sqrt_approx(sq), 0.0f);
                }
                {
                    float dx = xi - sx[jj+3], dy = yi - sy[jj+3], dz = zi - sz[jj+3];
                    float sq = fmaf(dz, dz, fmaf(dy, dy, dx * dx));
                    acc3 += fmaxf(0.8f - sqrt_approx(sq), 0.0f);
                }
            }
        }

        red[t] = (acc0 + acc1) + (acc2 + acc3);
        __syncthreads();
        #pragma unroll
        for (int s = TPB / 2; s > 0; s >>= 1) {
            if (t < s) red[t] += red[t + s];
            __syncthreads();
        }
        if (t == 0) g_pair_partial[idx] = (double)red[0];
    }
}

__global__ void dp_combine_kernel(float* __restrict__ out) {
    const int l = threadIdx.x;  // one warp
    // deterministic fixed-assignment sum of pairwise partials
    double s = 0.0;
    for (int i = l; i < NTILES; i += 32) s += g_pair_partial[i];
    #pragma unroll
    for (int o = 16; o; o >>= 1) s += __shfl_down_sync(0xffffffffu, s, o);
    if (l == 0) {
        double punish = s / NPAIRS_D;
        double var = (g_sumsq_d - g_sum_d * g_sum_d / (double)NTOT) / (double)(NTOT - 1);
        double sd  = sqrt(var);
        float q1 = 0.25f * g_qv[0] + 0.75f * g_qv[1];
        float q3 = 0.75f * g_qv[2] + 0.25f * g_qv[3];
        double dstd = sd - RAND_STD;
        double diqr = (double)(q3 - q1) - IQR_RAND;
        out[0] = (float)(punish + dstd * dstd + diqr * diqr);
    }
}

extern "C" void kernel_launch(void* const* d_in, const int* in_sizes, int n_in,
                              void* d_out, int out_size) {
    (void)in_sizes; (void)n_in; (void)out_size;
    const float* g = (const float*)d_in[0];
    float* out = (float*)d_out;

    cudaFuncSetAttribute(dp_main_kernel,
                         cudaFuncAttributeMaxDynamicSharedMemorySize, SMEM_BYTES);
    dp_main_kernel<<<GRID, TPB, SMEM_BYTES>>>(g);
    dp_combine_kernel<<<1, 32>>>(out);
}